// round 8
// baseline (speedup 1.0000x reference)
#include <cuda_runtime.h>

#define NSEQ 512
#define DFEAT 48
#define DH 96
#define TPB 128
#define W2STRIDE 772   // floats per o-plane: 96*8 + 4 pad -> octet lanes bank-staggered

// Factored first-layer projections (no allocs allowed -> device globals).
// g_A[b][i][k]  = sum_c x[b,i,c]*W1[c,k] + b1[k]
// g_Bt[b][k][j] = sum_c x[b,j,c]*W1[48+c,k]   (j-contiguous => LDG.128 per thread)
__device__ float g_A[4 * NSEQ * DH];
__device__ float g_Bt[4 * DH * NSEQ];

__global__ void precompute_kernel(const float* __restrict__ x,
                                  const float* __restrict__ W1,
                                  const float* __restrict__ b1) {
    int row = blockIdx.x;            // b*N + i
    int b = row >> 9;
    int i = row & (NSEQ - 1);
    __shared__ float sx[DFEAT];
    int t = threadIdx.x;             // 0..95 (output channel k)
    if (t < DFEAT) sx[t] = x[row * DFEAT + t];
    __syncthreads();
    float a = b1[t];
    float bb = 0.f;
#pragma unroll
    for (int c = 0; c < DFEAT; c++) {
        float xv = sx[c];
        a  = fmaf(xv, W1[c * DH + t], a);
        bb = fmaf(xv, W1[(DFEAT + c) * DH + t], bb);
    }
    g_A[row * DH + t] = a;
    g_Bt[(b * DH + t) * NSEQ + i] = bb;
}

// Branchless exact-GELU: erf via Abramowitz-Stegun 7.1.26 (|err| <= 1.5e-7).
__device__ __forceinline__ float gelu_fast(float x) {
    float ax = fabsf(x);
    float e = exp2f(x * x * -0.72134752044448170368f);
    float kd = fmaf(0.23164408767166038f, ax, 1.0f);
    float k;
    asm("rcp.approx.f32 %0, %1;" : "=f"(k) : "f"(kd));
    float q = fmaf(k, 1.061405429f, -1.453152027f);
    q = fmaf(k, q, 1.421413741f);
    q = fmaf(k, q, -0.284496736f);
    q = fmaf(k, q, 0.254829592f);
    float E = fmaf(-(k * q), e, 1.0f);        // erf(|x|/sqrt2)
    return fmaf(0.5f * ax, E, 0.5f * x);
}

__device__ __forceinline__ unsigned long long bcast2(float v) {
    unsigned long long r;
    asm("mov.b64 %0, {%1, %1};" : "=l"(r) : "r"(__float_as_uint(v)));
    return r;
}

// One CTA per output row (b,i). 128 threads = 16 j-slots x 8 feature-lanes.
// Lane o (=lane&7) owns features [o*6, o*6+6). Each j-slot owns 4 consecutive
// j's. Per k-group of 8, lane o computes gelu for k=k0+o (its 4 j's) and the
// octet exchanges h via a padded smem stage (slot js*9+o, conflict-free).
// W2 lives in smem as 8 o-planes (stride 772 floats) so each octet LDS hits
// staggered banks. Accumulators: p2 = 4x3 u64 (24 regs) -> 6 CTAs/SM.
__global__ void __launch_bounds__(TPB, 6) pair_kernel(const float* __restrict__ W2,
                                                      const float* __restrict__ b2,
                                                      float* __restrict__ out) {
    const int i = (int)(gridDim.x - 1 - blockIdx.x);   // longest rows first
    const int b = blockIdx.y;
    const int tid = threadIdx.x;
    const int w = tid >> 5;                // warp
    const int lane = tid & 31;
    const int o = lane & 7;                // feature octant / k-owner within octet
    const int js = lane >> 3;              // jslot within warp: 0..3
    const int jslot = (w << 2) | js;       // 0..15

    __shared__ __align__(16) float sW2p[8 * W2STRIDE];   // ~24.7 KB
    __shared__ __align__(16) float sA[DH];
    __shared__ __align__(16) float sb2[DFEAT];
    __shared__ __align__(16) float hstage[2][4][36][4];  // parity, warp, js*9+o, 4 j's
    __shared__ float red_m[4], red_s[4];
    __shared__ __align__(16) float red_o[4][DFEAT];

    // W2 -> o-planes: sW2p[o*W2STRIDE + k*8 + f] = W2[k][o*6+f], f<6
    for (int t = tid; t < DH * DFEAT; t += TPB) {
        int kk = t / DFEAT;
        int f  = t % DFEAT;
        int oo = f / 6;
        int ff = f - oo * 6;
        sW2p[oo * W2STRIDE + kk * 8 + ff] = W2[t];
    }
    if (tid < DH)    sA[tid]  = g_A[(b * NSEQ + i) * DH + tid];
    if (tid < DFEAT) sb2[tid] = b2[tid];
    __syncthreads();

    const float* __restrict__ Btb = g_Bt + b * DH * NSEQ + o * NSEQ;  // row o base
    const unsigned long long* __restrict__ b2p =
        (const unsigned long long*)(sb2 + o * 6);    // this lane's 6 feats (3 u64)
    const float* __restrict__ wplane = sW2p + o * W2STRIDE;

    float m = -1e30f, s = 0.f;
    unsigned long long o2[3];
#pragma unroll
    for (int r = 0; r < 3; r++) o2[r] = 0ull;
    const unsigned full = 0xffffffffu;

    for (int jbase = 0; jbase <= i; jbase += 64) {
        const int j0 = jbase + (jslot << 2);          // this thread's 4 j's

        unsigned long long p2[4][3];
#pragma unroll
        for (int jt = 0; jt < 4; jt++)
#pragma unroll
            for (int r = 0; r < 3; r++) p2[jt][r] = b2p[r];

        float4 cur = *(const float4*)(Btb + j0);      // prefetch g=0

#pragma unroll 1
        for (int g = 0; g < DH / 8; g++) {            // 12 groups of 8 k's
            const float4 bv = cur;
            if (g < DH / 8 - 1)                        // prefetch next group's row
                cur = *(const float4*)(Btb + (g + 1) * 8 * NSEQ + j0);

            const float av = sA[(g << 3) + o];
            float4 h4;
            h4.x = gelu_fast(av + bv.x);
            h4.y = gelu_fast(av + bv.y);
            h4.z = gelu_fast(av + bv.z);
            h4.w = gelu_fast(av + bv.w);
            const int par = g & 1;
            *(float4*)&hstage[par][w][js * 9 + o][0] = h4;
            __syncwarp();

            const float* wk = wplane + (g << 6);       // k0*8 floats = g*64
#pragma unroll
            for (int u = 0; u < 8; u++) {
                float4 hu = *(const float4*)&hstage[par][w][js * 9 + u][0];
                unsigned long long h2_0 = bcast2(hu.x);
                unsigned long long h2_1 = bcast2(hu.y);
                unsigned long long h2_2 = bcast2(hu.z);
                unsigned long long h2_3 = bcast2(hu.w);
                // W2 row k=g*8+u, this lane's 6 feats: LDS.128 + LDS.64
                ulonglong2 wva = *(const ulonglong2*)(wk + u * 8);
                unsigned long long wvb = *(const unsigned long long*)(wk + u * 8 + 4);
                asm("fma.rn.f32x2 %0, %1, %2, %0;" : "+l"(p2[0][0]) : "l"(h2_0), "l"(wva.x));
                asm("fma.rn.f32x2 %0, %1, %2, %0;" : "+l"(p2[0][1]) : "l"(h2_0), "l"(wva.y));
                asm("fma.rn.f32x2 %0, %1, %2, %0;" : "+l"(p2[0][2]) : "l"(h2_0), "l"(wvb));
                asm("fma.rn.f32x2 %0, %1, %2, %0;" : "+l"(p2[1][0]) : "l"(h2_1), "l"(wva.x));
                asm("fma.rn.f32x2 %0, %1, %2, %0;" : "+l"(p2[1][1]) : "l"(h2_1), "l"(wva.y));
                asm("fma.rn.f32x2 %0, %1, %2, %0;" : "+l"(p2[1][2]) : "l"(h2_1), "l"(wvb));
                asm("fma.rn.f32x2 %0, %1, %2, %0;" : "+l"(p2[2][0]) : "l"(h2_2), "l"(wva.x));
                asm("fma.rn.f32x2 %0, %1, %2, %0;" : "+l"(p2[2][1]) : "l"(h2_2), "l"(wva.y));
                asm("fma.rn.f32x2 %0, %1, %2, %0;" : "+l"(p2[2][2]) : "l"(h2_2), "l"(wvb));
                asm("fma.rn.f32x2 %0, %1, %2, %0;" : "+l"(p2[3][0]) : "l"(h2_3), "l"(wva.x));
                asm("fma.rn.f32x2 %0, %1, %2, %0;" : "+l"(p2[3][1]) : "l"(h2_3), "l"(wva.y));
                asm("fma.rn.f32x2 %0, %1, %2, %0;" : "+l"(p2[3][2]) : "l"(h2_3), "l"(wvb));
            }
        }

        // per-j norms: own 6 features, then octet-sum (all octet lanes converge
        // to identical totals -> identical m,s trajectories)
        float wgt[4];
#pragma unroll
        for (int jt = 0; jt < 4; jt++) {
            unsigned long long n2 = 0ull;
#pragma unroll
            for (int r = 0; r < 3; r++)
                asm("fma.rn.f32x2 %0, %1, %1, %0;" : "+l"(n2) : "l"(p2[jt][r]));
            unsigned lo, hi;
            asm("mov.b64 {%0, %1}, %2;" : "=r"(lo), "=r"(hi) : "l"(n2));
            float n = __uint_as_float(lo) + __uint_as_float(hi);
            n += __shfl_xor_sync(full, n, 1, 8);
            n += __shfl_xor_sync(full, n, 2, 8);
            n += __shfl_xor_sync(full, n, 4, 8);
            wgt[jt] = (j0 + jt <= i) ? sqrtf(n) : -1e30f;
        }

        // online softmax merge of 4 new scores
        float mN = fmaxf(fmaxf(wgt[0], wgt[1]), fmaxf(wgt[2], wgt[3]));
        mN = fmaxf(m, mN);
        float c = __expf(m - mN);
        float e[4];
#pragma unroll
        for (int jt = 0; jt < 4; jt++) e[jt] = __expf(wgt[jt] - mN);  // 0 if masked
        s = s * c + ((e[0] + e[1]) + (e[2] + e[3]));
        m = mN;
        unsigned long long c2 = bcast2(c);
#pragma unroll
        for (int r = 0; r < 3; r++)
            asm("mul.rn.f32x2 %0, %0, %1;" : "+l"(o2[r]) : "l"(c2));
#pragma unroll
        for (int jt = 0; jt < 4; jt++) {
            unsigned long long e2 = bcast2(e[jt]);
#pragma unroll
            for (int r = 0; r < 3; r++)
                asm("fma.rn.f32x2 %0, %1, %2, %0;" : "+l"(o2[r]) : "l"(p2[jt][r]), "l"(e2));
        }
    }

    // ---- reduce across the 4 j-slots in each warp (preserving o lanes) ----
#pragma unroll
    for (int off = 8; off <= 16; off <<= 1) {
        float mo = __shfl_xor_sync(full, m, off);
        float so = __shfl_xor_sync(full, s, off);
        float mN = fmaxf(m, mo);
        float fs = __expf(m - mN);
        float fo = __expf(mo - mN);
        s = s * fs + so * fo;
        unsigned long long fs2 = bcast2(fs), fo2 = bcast2(fo);
#pragma unroll
        for (int r = 0; r < 3; r++) {
            unsigned long long t = __shfl_xor_sync(full, o2[r], off);
            asm("mul.rn.f32x2 %0, %0, %1;"     : "+l"(o2[r]) : "l"(fs2));
            asm("fma.rn.f32x2 %0, %1, %2, %0;" : "+l"(o2[r]) : "l"(t), "l"(fo2));
        }
        m = mN;
    }

    if (lane < 8) {                       // lanes 0..7 hold o=0..7 warp results
        if (lane == 0) { red_m[w] = m; red_s[w] = s; }
        unsigned long long* dst = (unsigned long long*)(&red_o[w][o * 6]);
#pragma unroll
        for (int r = 0; r < 3; r++) dst[r] = o2[r];
    }
    __syncthreads();

    if (tid < DFEAT) {
        float M = fmaxf(fmaxf(red_m[0], red_m[1]), fmaxf(red_m[2], red_m[3]));
        float S = 0.f, O = 0.f;
#pragma unroll
        for (int ww = 0; ww < 4; ww++) {
            float f = __expf(red_m[ww] - M);   // 0 for fully idle warps
            S += red_s[ww] * f;
            O += red_o[ww][tid] * f;
        }
        out[(b * NSEQ + i) * DFEAT + tid] = O / S;
    }
}

extern "C" void kernel_launch(void* const* d_in, const int* in_sizes, int n_in,
                              void* d_out, int out_size) {
    const float* x  = (const float*)d_in[0];
    const float* W1 = (const float*)d_in[1];
    const float* b1 = (const float*)d_in[2];
    const float* W2 = (const float*)d_in[3];
    const float* b2 = (const float*)d_in[4];
    float* out = (float*)d_out;

    precompute_kernel<<<4 * NSEQ, DH>>>(x, W1, b1);
    dim3 grid(NSEQ, 4);
    pair_kernel<<<grid, TPB>>>(W2, b2, out);
}

// round 11
// speedup vs baseline: 1.6357x; 1.6357x over previous
#include <cuda_runtime.h>
#include <cuda_bf16.h>
#include <cstdint>

#define NSEQ 512
#define DFEAT 48
#define DH 96
#define TPB 128

// Factored first-layer projections.
// g_A[b][i][k] = sum_c x[b,i,c]*W1[c,k] + b1[k]
// g_B[b][j][k] = sum_c x[b,j,c]*W1[48+c,k]   (row-major [j][k] for fragment loads)
__device__ float g_A[4 * NSEQ * DH];
__device__ float g_B[4 * NSEQ * DH];

__global__ void precompute_kernel(const float* __restrict__ x,
                                  const float* __restrict__ W1,
                                  const float* __restrict__ b1) {
    int row = blockIdx.x;            // b*N + i
    __shared__ float sx[DFEAT];
    int t = threadIdx.x;             // 0..95
    if (t < DFEAT) sx[t] = x[row * DFEAT + t];
    __syncthreads();
    float a = b1[t];
    float bb = 0.f;
#pragma unroll
    for (int c = 0; c < DFEAT; c++) {
        float xv = sx[c];
        a  = fmaf(xv, W1[c * DH + t], a);
        bb = fmaf(xv, W1[(DFEAT + c) * DH + t], bb);
    }
    g_A[row * DH + t] = a;
    g_B[row * DH + t] = bb;
}

// Branchless exact-GELU: erf via Abramowitz-Stegun 7.1.26 (|err| <= 1.5e-7).
__device__ __forceinline__ float gelu_fast(float x) {
    float ax = fabsf(x);
    float e = exp2f(x * x * -0.72134752044448170368f);
    float kd = fmaf(0.23164408767166038f, ax, 1.0f);
    float k;
    asm("rcp.approx.f32 %0, %1;" : "=f"(k) : "f"(kd));
    float q = fmaf(k, 1.061405429f, -1.453152027f);
    q = fmaf(k, q, 1.421413741f);
    q = fmaf(k, q, -0.284496736f);
    q = fmaf(k, q, 0.254829592f);
    float E = fmaf(-(k * q), e, 1.0f);
    return fmaf(0.5f * ax, E, 0.5f * x);
}

__device__ __forceinline__ unsigned long long bcast2(float v) {
    unsigned long long r;
    asm("mov.b64 %0, {%1, %1};" : "=l"(r) : "r"(__float_as_uint(v)));
    return r;
}
__device__ __forceinline__ unsigned long long pack2(float lo, float hi) {
    unsigned long long r;
    asm("mov.b64 %0, {%1, %2};" : "=l"(r) : "r"(__float_as_uint(lo)), "r"(__float_as_uint(hi)));
    return r;
}
// bf16x2 pack: element0(low)=lo, element1(high)=hi  (cvt puts 2nd src in low half)
__device__ __forceinline__ uint32_t packbf(float lo, float hi) {
    uint32_t d;
    asm("cvt.rn.bf16x2.f32 %0, %1, %2;" : "=r"(d) : "f"(hi), "f"(lo));
    return d;
}
// residue pack: (f - bf16(f)) for both halves of hw
__device__ __forceinline__ uint32_t packlo(float f0, float f1, uint32_t hw) {
    float r0 = f0 - __uint_as_float(hw << 16);
    float r1 = f1 - __uint_as_float(hw & 0xffff0000u);
    return packbf(r0, r1);
}

__device__ __forceinline__ void hmma(float* c, uint32_t a0, uint32_t a1,
                                     uint32_t a2, uint32_t a3,
                                     uint32_t b0, uint32_t b1) {
    asm volatile(
        "mma.sync.aligned.m16n8k16.row.col.f32.bf16.bf16.f32 "
        "{%0,%1,%2,%3}, {%4,%5,%6,%7}, {%8,%9}, {%0,%1,%2,%3};"
        : "+f"(c[0]), "+f"(c[1]), "+f"(c[2]), "+f"(c[3])
        : "r"(a0), "r"(a1), "r"(a2), "r"(a3), "r"(b0), "r"(b1));
}

// One CTA per output row (b,i). 4 warps; per 128-j tile warp w owns rows
// jbase+w*32..+31 as two m16 fragments. Each thread computes the 8 gelu h
// values of its own A-fragment directly (no exchange), splits hi/lo bf16, and
// accumulates p = h@W2 via 3 HMMA passes (hi*hi + lo*hi + hi*lo) in fp32.
// C-fragment: thread owns rows r,r+8 and cols {8n+2q, 8n+2q+1}, n=0..5.
__global__ void __launch_bounds__(TPB, 4) pair_kernel(const float* __restrict__ W2,
                                                      const float* __restrict__ b2,
                                                      float* __restrict__ out) {
    const int i = (int)(gridDim.x - 1 - blockIdx.x);   // longest rows first
    const int b = blockIdx.y;
    const int tid = threadIdx.x;
    const int w = tid >> 5;
    const int lane = tid & 31;
    const int q = lane & 3;        // threadID within group of 4
    const int r = lane >> 2;       // group id 0..7

    __shared__ __align__(16) unsigned long long sBhi[36 * 32];  // 9 KB
    __shared__ __align__(16) unsigned long long sBlo[36 * 32];  // 9 KB
    __shared__ __align__(16) float sA[DH];
    __shared__ float red_m[4], red_s[4];
    __shared__ __align__(16) float red_o[4][DFEAT];

    // Stage W2 B-fragments (hi/lo) per (ktile, ntile, lane).
    // b0 = {W2[k0][n], W2[k0+1][n]}, b1 = {W2[k0+8][n], W2[k0+9][n]}, k0=16kt+2q, n=8nt+r
    for (int t36 = w; t36 < 36; t36 += 4) {
        int kt = t36 / 6, nt = t36 - kt * 6;
        int k0 = 16 * kt + 2 * q;
        int n = 8 * nt + r;
        float w00 = W2[k0 * DFEAT + n];
        float w01 = W2[(k0 + 1) * DFEAT + n];
        float w10 = W2[(k0 + 8) * DFEAT + n];
        float w11 = W2[(k0 + 9) * DFEAT + n];
        uint32_t b0h = packbf(w00, w01);
        uint32_t b1h = packbf(w10, w11);
        uint32_t b0l = packlo(w00, w01, b0h);
        uint32_t b1l = packlo(w10, w11, b1h);
        unsigned long long vh, vl;
        asm("mov.b64 %0, {%1, %2};" : "=l"(vh) : "r"(b0h), "r"(b1h));
        asm("mov.b64 %0, {%1, %2};" : "=l"(vl) : "r"(b0l), "r"(b1l));
        sBhi[t36 * 32 + lane] = vh;
        sBlo[t36 * 32 + lane] = vl;
    }
    if (tid < DH) sA[tid] = g_A[(b * NSEQ + i) * DH + tid];

    unsigned long long b2f[6];
#pragma unroll
    for (int nt = 0; nt < 6; nt++)
        b2f[nt] = pack2(b2[8 * nt + 2 * q], b2[8 * nt + 2 * q + 1]);
    __syncthreads();

    const float* __restrict__ Bbase = g_B + (size_t)(b * NSEQ) * DH;
    const unsigned full = 0xffffffffu;

    float m = -1e30f, s = 0.f;
    unsigned long long o2[6];
#pragma unroll
    for (int nt = 0; nt < 6; nt++) o2[nt] = 0ull;

    for (int jbase = 0; jbase <= i; jbase += 128) {
#pragma unroll
        for (int mt = 0; mt < 2; mt++) {
            const int j0 = jbase + w * 32 + mt * 16;
            float acc[6][4];
#pragma unroll
            for (int nt = 0; nt < 6; nt++)
#pragma unroll
                for (int e = 0; e < 4; e++) acc[nt][e] = 0.f;

#pragma unroll
            for (int kt = 0; kt < 6; kt++) {
                const int c0 = 16 * kt + 2 * q;
                float2 aP0 = *(const float2*)&sA[c0];
                float2 aP1 = *(const float2*)&sA[c0 + 8];
                const float* rowA = Bbase + (size_t)(j0 + r) * DH + c0;
                const float* rowB = rowA + 8 * DH;
                float2 x00 = *(const float2*)rowA;        // row r,   k c0..c0+1
                float2 x01 = *(const float2*)(rowA + 8);  // row r,   k c0+8..+9
                float2 x10 = *(const float2*)rowB;        // row r+8
                float2 x11 = *(const float2*)(rowB + 8);
                float h00 = gelu_fast(aP0.x + x00.x);
                float h01 = gelu_fast(aP0.y + x00.y);
                float h02 = gelu_fast(aP1.x + x01.x);
                float h03 = gelu_fast(aP1.y + x01.y);
                float h10 = gelu_fast(aP0.x + x10.x);
                float h11 = gelu_fast(aP0.y + x10.y);
                float h12 = gelu_fast(aP1.x + x11.x);
                float h13 = gelu_fast(aP1.y + x11.y);
                // A frags: a0=A[r][2q..], a1=A[r+8][2q..], a2=A[r][2q+8..], a3=A[r+8][2q+8..]
                uint32_t a0h = packbf(h00, h01), a1h = packbf(h10, h11);
                uint32_t a2h = packbf(h02, h03), a3h = packbf(h12, h13);
                uint32_t a0l = packlo(h00, h01, a0h), a1l = packlo(h10, h11, a1h);
                uint32_t a2l = packlo(h02, h03, a2h), a3l = packlo(h12, h13, a3h);

#pragma unroll
                for (int nt = 0; nt < 6; nt++) {
                    unsigned long long vh = sBhi[(kt * 6 + nt) * 32 + lane];
                    unsigned long long vl = sBlo[(kt * 6 + nt) * 32 + lane];
                    uint32_t b0h, b1h, b0l, b1l;
                    asm("mov.b64 {%0, %1}, %2;" : "=r"(b0h), "=r"(b1h) : "l"(vh));
                    asm("mov.b64 {%0, %1}, %2;" : "=r"(b0l), "=r"(b1l) : "l"(vl));
                    hmma(acc[nt], a0h, a1h, a2h, a3h, b0h, b1h);
                    hmma(acc[nt], a0l, a1l, a2l, a3l, b0h, b1h);
                    hmma(acc[nt], a0h, a1h, a2h, a3h, b0l, b1l);
                }
            }

            // ---- epilogue for this m16 tile: rows jA=j0+r, jB=j0+r+8 ----
            unsigned long long pA[6], pB[6];
            unsigned long long nA2 = 0ull, nB2 = 0ull;
#pragma unroll
            for (int nt = 0; nt < 6; nt++) {
                unsigned long long da = pack2(acc[nt][0], acc[nt][1]);
                unsigned long long db = pack2(acc[nt][2], acc[nt][3]);
                asm("add.rn.f32x2 %0, %1, %2;" : "=l"(pA[nt]) : "l"(da), "l"(b2f[nt]));
                asm("add.rn.f32x2 %0, %1, %2;" : "=l"(pB[nt]) : "l"(db), "l"(b2f[nt]));
                asm("fma.rn.f32x2 %0, %1, %1, %0;" : "+l"(nA2) : "l"(pA[nt]));
                asm("fma.rn.f32x2 %0, %1, %1, %0;" : "+l"(nB2) : "l"(pB[nt]));
            }
            unsigned lo, hi;
            asm("mov.b64 {%0, %1}, %2;" : "=r"(lo), "=r"(hi) : "l"(nA2));
            float nA = __uint_as_float(lo) + __uint_as_float(hi);
            asm("mov.b64 {%0, %1}, %2;" : "=r"(lo), "=r"(hi) : "l"(nB2));
            float nB = __uint_as_float(lo) + __uint_as_float(hi);
            nA += __shfl_xor_sync(full, nA, 1, 4);
            nA += __shfl_xor_sync(full, nA, 2, 4);
            nB += __shfl_xor_sync(full, nB, 1, 4);
            nB += __shfl_xor_sync(full, nB, 2, 4);
            const int jA = j0 + r, jB = j0 + r + 8;
            float wA = (jA <= i) ? sqrtf(nA) : -1e30f;
            float wB = (jB <= i) ? sqrtf(nB) : -1e30f;

            float mN = fmaxf(m, fmaxf(wA, wB));
            float c  = __expf(m - mN);
            float eA = __expf(wA - mN);
            float eB = __expf(wB - mN);
            s = s * c + eA + eB;
            m = mN;
            unsigned long long c2 = bcast2(c), eA2 = bcast2(eA), eB2 = bcast2(eB);
#pragma unroll
            for (int nt = 0; nt < 6; nt++) {
                asm("mul.rn.f32x2 %0, %0, %1;"     : "+l"(o2[nt]) : "l"(c2));
                asm("fma.rn.f32x2 %0, %1, %2, %0;" : "+l"(o2[nt]) : "l"(pA[nt]), "l"(eA2));
                asm("fma.rn.f32x2 %0, %1, %2, %0;" : "+l"(o2[nt]) : "l"(pB[nt]), "l"(eB2));
            }
        }
    }

    // ---- merge the 8 r-groups within each warp (preserving q feature lanes) ----
#pragma unroll
    for (int off = 4; off <= 16; off <<= 1) {
        float mo = __shfl_xor_sync(full, m, off);
        float so = __shfl_xor_sync(full, s, off);
        float mN = fmaxf(m, mo);
        float fs = __expf(m - mN);
        float fo = __expf(mo - mN);
        s = s * fs + so * fo;
        unsigned long long fs2 = bcast2(fs), fo2 = bcast2(fo);
#pragma unroll
        for (int nt = 0; nt < 6; nt++) {
            unsigned long long t = __shfl_xor_sync(full, o2[nt], off);
            asm("mul.rn.f32x2 %0, %0, %1;"     : "+l"(o2[nt]) : "l"(fs2));
            asm("fma.rn.f32x2 %0, %1, %2, %0;" : "+l"(o2[nt]) : "l"(t), "l"(fo2));
        }
        m = mN;
    }

    if (lane < 4) {                    // lanes 0..3 carry q=0..3 warp results
        if (lane == 0) { red_m[w] = m; red_s[w] = s; }
#pragma unroll
        for (int nt = 0; nt < 6; nt++) {
            unsigned lo, hi;
            asm("mov.b64 {%0, %1}, %2;" : "=r"(lo), "=r"(hi) : "l"(o2[nt]));
            red_o[w][8 * nt + 2 * q]     = __uint_as_float(lo);
            red_o[w][8 * nt + 2 * q + 1] = __uint_as_float(hi);
        }
    }
    __syncthreads();

    if (tid < DFEAT) {
        float M = fmaxf(fmaxf(red_m[0], red_m[1]), fmaxf(red_m[2], red_m[3]));
        float S = 0.f, O = 0.f;
#pragma unroll
        for (int ww = 0; ww < 4; ww++) {
            float f = __expf(red_m[ww] - M);   // 0 for fully idle warps
            S += red_s[ww] * f;
            O += red_o[ww][tid] * f;
        }
        out[(b * NSEQ + i) * DFEAT + tid] = O / S;
    }
}

extern "C" void kernel_launch(void* const* d_in, const int* in_sizes, int n_in,
                              void* d_out, int out_size) {
    const float* x  = (const float*)d_in[0];
    const float* W1 = (const float*)d_in[1];
    const float* b1 = (const float*)d_in[2];
    const float* W2 = (const float*)d_in[3];
    const float* b2 = (const float*)d_in[4];
    float* out = (float*)d_out;

    precompute_kernel<<<4 * NSEQ, DH>>>(x, W1, b1);
    dim3 grid(NSEQ, 4);
    pair_kernel<<<grid, TPB>>>(W2, b2, out);
}

// round 12
// speedup vs baseline: 1.8845x; 1.1521x over previous
#include <cuda_runtime.h>
#include <cuda_bf16.h>
#include <cstdint>

#define NSEQ 512
#define DFEAT 48
#define DH 96
#define TPB 128

// Factored first-layer projections.
// g_A[b][i][k] = sum_c x[b,i,c]*W1[c,k] + b1[k]
// g_B[b][j][k] = sum_c x[b,j,c]*W1[48+c,k]
__device__ float g_A[4 * NSEQ * DH];
__device__ float g_B[4 * NSEQ * DH];

__global__ void precompute_kernel(const float* __restrict__ x,
                                  const float* __restrict__ W1,
                                  const float* __restrict__ b1) {
    int row = blockIdx.x;            // b*N + i
    __shared__ float sx[DFEAT];
    int t = threadIdx.x;             // 0..95
    if (t < DFEAT) sx[t] = x[row * DFEAT + t];
    __syncthreads();
    float a = b1[t];
    float bb = 0.f;
#pragma unroll
    for (int c = 0; c < DFEAT; c++) {
        float xv = sx[c];
        a  = fmaf(xv, W1[c * DH + t], a);
        bb = fmaf(xv, W1[(DFEAT + c) * DH + t], bb);
    }
    g_A[row * DH + t] = a;
    g_B[row * DH + t] = bb;
}

__device__ __forceinline__ unsigned long long bcast2(float v) {
    unsigned long long r;
    asm("mov.b64 %0, {%1, %1};" : "=l"(r) : "r"(__float_as_uint(v)));
    return r;
}
__device__ __forceinline__ unsigned long long pack2(float lo, float hi) {
    unsigned long long r;
    asm("mov.b64 %0, {%1, %2};" : "=l"(r) : "r"(__float_as_uint(lo)), "r"(__float_as_uint(hi)));
    return r;
}
__device__ __forceinline__ uint32_t packbf(float lo, float hi) {
    uint32_t d;
    asm("cvt.rn.bf16x2.f32 %0, %1, %2;" : "=r"(d) : "f"(hi), "f"(lo));
    return d;
}

// Packed-constant bundle for the f32x2 gelu chain (hoisted to registers).
struct GC {
    unsigned long long nl, Aa, one2, half2, p5, p4, p3, p2, p1;
};

// Branchless exact-GELU on a packed pair (A-S 7.1.26 erf, |err|<=1.5e-7).
__device__ __forceinline__ unsigned long long gelu2(unsigned long long x2, const GC& C) {
    unsigned long long ax2, xx2, t2, e2p, kd2, k2, q2, kq2, E2, in2, g2;
    asm("and.b64 %0, %1, 0x7FFFFFFF7FFFFFFF;" : "=l"(ax2) : "l"(x2));
    asm("mul.rn.f32x2 %0, %1, %1;" : "=l"(xx2) : "l"(x2));
    asm("mul.rn.f32x2 %0, %1, %2;" : "=l"(t2) : "l"(xx2), "l"(C.nl));
    uint32_t tl, th;
    asm("mov.b64 {%0,%1}, %2;" : "=r"(tl), "=r"(th) : "l"(t2));
    float e0, e1;
    asm("ex2.approx.f32 %0, %1;" : "=f"(e0) : "f"(__uint_as_float(tl)));
    asm("ex2.approx.f32 %0, %1;" : "=f"(e1) : "f"(__uint_as_float(th)));
    e2p = pack2(e0, e1);
    asm("fma.rn.f32x2 %0, %1, %2, %3;" : "=l"(kd2) : "l"(ax2), "l"(C.Aa), "l"(C.one2));
    uint32_t kl, kh;
    asm("mov.b64 {%0,%1}, %2;" : "=r"(kl), "=r"(kh) : "l"(kd2));
    float k0f, k1f;
    asm("rcp.approx.f32 %0, %1;" : "=f"(k0f) : "f"(__uint_as_float(kl)));
    asm("rcp.approx.f32 %0, %1;" : "=f"(k1f) : "f"(__uint_as_float(kh)));
    k2 = pack2(k0f, k1f);
    asm("fma.rn.f32x2 %0, %1, %2, %3;" : "=l"(q2) : "l"(k2), "l"(C.p5), "l"(C.p4));
    asm("fma.rn.f32x2 %0, %1, %2, %3;" : "=l"(q2) : "l"(k2), "l"(q2), "l"(C.p3));
    asm("fma.rn.f32x2 %0, %1, %2, %3;" : "=l"(q2) : "l"(k2), "l"(q2), "l"(C.p2));
    asm("fma.rn.f32x2 %0, %1, %2, %3;" : "=l"(q2) : "l"(k2), "l"(q2), "l"(C.p1));
    asm("mul.rn.f32x2 %0, %1, %2;" : "=l"(kq2) : "l"(k2), "l"(q2));
    asm("xor.b64 %0, %1, 0x8000000080000000;" : "=l"(kq2) : "l"(kq2));
    asm("fma.rn.f32x2 %0, %1, %2, %3;" : "=l"(E2) : "l"(kq2), "l"(e2p), "l"(C.one2));
    asm("fma.rn.f32x2 %0, %1, %2, %3;" : "=l"(in2) : "l"(ax2), "l"(E2), "l"(x2));
    asm("mul.rn.f32x2 %0, %1, %2;" : "=l"(g2) : "l"(in2), "l"(C.half2));
    return g2;
}

// Split a packed gelu pair (g0,g1) into bf16x2 hi word + bf16x2 residue word.
__device__ __forceinline__ void tosplit(unsigned long long g2, uint32_t& hw, uint32_t& lw) {
    uint32_t g0, g1;
    asm("mov.b64 {%0,%1}, %2;" : "=r"(g0), "=r"(g1) : "l"(g2));
    hw = packbf(__uint_as_float(g0), __uint_as_float(g1));
    unsigned long long hi2 = pack2(__uint_as_float(hw << 16),
                                   __uint_as_float(hw & 0xffff0000u));
    unsigned long long r2;
    asm("sub.rn.f32x2 %0, %1, %2;" : "=l"(r2) : "l"(g2), "l"(hi2));
    uint32_t r0, r1;
    asm("mov.b64 {%0,%1}, %2;" : "=r"(r0), "=r"(r1) : "l"(r2));
    lw = packbf(__uint_as_float(r0), __uint_as_float(r1));
}

__device__ __forceinline__ void hmma(float* c, uint32_t a0, uint32_t a1,
                                     uint32_t a2, uint32_t a3,
                                     uint32_t b0, uint32_t b1) {
    asm volatile(
        "mma.sync.aligned.m16n8k16.row.col.f32.bf16.bf16.f32 "
        "{%0,%1,%2,%3}, {%4,%5,%6,%7}, {%8,%9}, {%0,%1,%2,%3};"
        : "+f"(c[0]), "+f"(c[1]), "+f"(c[2]), "+f"(c[3])
        : "r"(a0), "r"(a1), "r"(a2), "r"(a3), "r"(b0), "r"(b1));
}

// One CTA per output row (b,i). 4 warps; per 128-j tile warp w owns rows
// jbase+w*32..+31 as two m16 fragments; fully-masked m16 tiles are skipped
// (warp-uniform). gelu computed packed f32x2, split hi/lo bf16, p = h@W2 via
// 3 HMMA passes (hi*hi + lo*hi + hi*lo) in fp32.
__global__ void __launch_bounds__(TPB, 4) pair_kernel(const float* __restrict__ W2,
                                                      const float* __restrict__ b2,
                                                      float* __restrict__ out) {
    const int i = (int)(gridDim.x - 1 - blockIdx.x);   // longest rows first
    const int b = blockIdx.y;
    const int tid = threadIdx.x;
    const int w = tid >> 5;
    const int lane = tid & 31;
    const int q = lane & 3;        // thread within group of 4
    const int r = lane >> 2;       // group id 0..7

    __shared__ __align__(16) unsigned long long sBhi[36 * 32];  // 9 KB
    __shared__ __align__(16) unsigned long long sBlo[36 * 32];  // 9 KB
    __shared__ __align__(16) float sA[DH];
    __shared__ __align__(16) float sb2[DFEAT];
    __shared__ float red_m[4], red_s[4];
    __shared__ __align__(16) float red_o[4][DFEAT];

    // Stage W2 B-fragments (hi/lo) per (ktile, ntile, lane).
    for (int t36 = w; t36 < 36; t36 += 4) {
        int kt = t36 / 6, nt = t36 - kt * 6;
        int k0 = 16 * kt + 2 * q;
        int n = 8 * nt + r;
        float w00 = W2[k0 * DFEAT + n];
        float w01 = W2[(k0 + 1) * DFEAT + n];
        float w10 = W2[(k0 + 8) * DFEAT + n];
        float w11 = W2[(k0 + 9) * DFEAT + n];
        uint32_t b0h = packbf(w00, w01);
        uint32_t b1h = packbf(w10, w11);
        uint32_t b0l = packbf(w00 - __uint_as_float(b0h << 16),
                              w01 - __uint_as_float(b0h & 0xffff0000u));
        uint32_t b1l = packbf(w10 - __uint_as_float(b1h << 16),
                              w11 - __uint_as_float(b1h & 0xffff0000u));
        unsigned long long vh, vl;
        asm("mov.b64 %0, {%1, %2};" : "=l"(vh) : "r"(b0h), "r"(b1h));
        asm("mov.b64 %0, {%1, %2};" : "=l"(vl) : "r"(b0l), "r"(b1l));
        sBhi[t36 * 32 + lane] = vh;
        sBlo[t36 * 32 + lane] = vl;
    }
    if (tid < DH)    sA[tid]  = g_A[(b * NSEQ + i) * DH + tid];
    if (tid < DFEAT) sb2[tid] = b2[tid];
    __syncthreads();

    GC C;
    C.nl = bcast2(-0.72134752044448170368f);
    C.Aa = bcast2(0.23164408767166038f);
    C.one2 = bcast2(1.0f);
    C.half2 = bcast2(0.5f);
    C.p5 = bcast2(1.061405429f);
    C.p4 = bcast2(-1.453152027f);
    C.p3 = bcast2(1.421413741f);
    C.p2 = bcast2(-0.284496736f);
    C.p1 = bcast2(0.254829592f);

    const float* __restrict__ Bbase = g_B + b * NSEQ * DH;
    const unsigned long long* __restrict__ b2v = (const unsigned long long*)sb2;
    const unsigned full = 0xffffffffu;

    float m = -1e30f, s = 0.f;
    unsigned long long o2[6];
#pragma unroll
    for (int nt = 0; nt < 6; nt++) o2[nt] = 0ull;

    for (int jbase = 0; jbase <= i; jbase += 128) {
#pragma unroll
        for (int mt = 0; mt < 2; mt++) {
            const int j0 = jbase + w * 32 + mt * 16;
            if (j0 > i) break;                 // warp-uniform tail skip

            float acc[6][4];
#pragma unroll
            for (int nt = 0; nt < 6; nt++)
#pragma unroll
                for (int e = 0; e < 4; e++) acc[nt][e] = 0.f;

#pragma unroll
            for (int kt = 0; kt < 6; kt++) {
                const int c0 = 16 * kt + 2 * q;
                unsigned long long a0 = *(const unsigned long long*)&sA[c0];
                unsigned long long a1 = *(const unsigned long long*)&sA[c0 + 8];
                const int ro = (j0 + r) * DH + c0;
                unsigned long long x00 = *(const unsigned long long*)(Bbase + ro);
                unsigned long long x01 = *(const unsigned long long*)(Bbase + ro + 8);
                unsigned long long x10 = *(const unsigned long long*)(Bbase + ro + 8 * DH);
                unsigned long long x11 = *(const unsigned long long*)(Bbase + ro + 8 * DH + 8);
                unsigned long long p00, p01, p10, p11;
                asm("add.rn.f32x2 %0, %1, %2;" : "=l"(p00) : "l"(a0), "l"(x00));
                asm("add.rn.f32x2 %0, %1, %2;" : "=l"(p01) : "l"(a1), "l"(x01));
                asm("add.rn.f32x2 %0, %1, %2;" : "=l"(p10) : "l"(a0), "l"(x10));
                asm("add.rn.f32x2 %0, %1, %2;" : "=l"(p11) : "l"(a1), "l"(x11));
                unsigned long long g00 = gelu2(p00, C);
                unsigned long long g01 = gelu2(p01, C);
                unsigned long long g10 = gelu2(p10, C);
                unsigned long long g11 = gelu2(p11, C);
                uint32_t a0h, a0l, a1h, a1l, a2h, a2l, a3h, a3l;
                tosplit(g00, a0h, a0l);    // A[r][2q..2q+1]
                tosplit(g10, a1h, a1l);    // A[r+8][2q..2q+1]
                tosplit(g01, a2h, a2l);    // A[r][2q+8..2q+9]
                tosplit(g11, a3h, a3l);    // A[r+8][2q+8..2q+9]

#pragma unroll
                for (int nt = 0; nt < 6; nt++) {
                    unsigned long long vh = sBhi[(kt * 6 + nt) * 32 + lane];
                    unsigned long long vl = sBlo[(kt * 6 + nt) * 32 + lane];
                    uint32_t b0h, b1h, b0l, b1l;
                    asm("mov.b64 {%0, %1}, %2;" : "=r"(b0h), "=r"(b1h) : "l"(vh));
                    asm("mov.b64 {%0, %1}, %2;" : "=r"(b0l), "=r"(b1l) : "l"(vl));
                    hmma(acc[nt], a0h, a1h, a2h, a3h, b0h, b1h);
                    hmma(acc[nt], a0l, a1l, a2l, a3l, b0h, b1h);
                    hmma(acc[nt], a0h, a1h, a2h, a3h, b0l, b1l);
                }
            }

            // ---- epilogue: rows jA=j0+r, jB=j0+r+8 ----
            unsigned long long nA2 = 0ull, nB2 = 0ull;
#pragma unroll
            for (int nt = 0; nt < 6; nt++) {
                unsigned long long bb = b2v[4 * nt + q];
                unsigned long long pa, pb;
                asm("add.rn.f32x2 %0, %1, %2;" : "=l"(pa)
                    : "l"(pack2(acc[nt][0], acc[nt][1])), "l"(bb));
                asm("add.rn.f32x2 %0, %1, %2;" : "=l"(pb)
                    : "l"(pack2(acc[nt][2], acc[nt][3])), "l"(bb));
                asm("fma.rn.f32x2 %0, %1, %1, %0;" : "+l"(nA2) : "l"(pa));
                asm("fma.rn.f32x2 %0, %1, %1, %0;" : "+l"(nB2) : "l"(pb));
            }
            unsigned lo, hi;
            asm("mov.b64 {%0, %1}, %2;" : "=r"(lo), "=r"(hi) : "l"(nA2));
            float nA = __uint_as_float(lo) + __uint_as_float(hi);
            asm("mov.b64 {%0, %1}, %2;" : "=r"(lo), "=r"(hi) : "l"(nB2));
            float nB = __uint_as_float(lo) + __uint_as_float(hi);
            nA += __shfl_xor_sync(full, nA, 1, 4);
            nA += __shfl_xor_sync(full, nA, 2, 4);
            nB += __shfl_xor_sync(full, nB, 1, 4);
            nB += __shfl_xor_sync(full, nB, 2, 4);
            const int jA = j0 + r, jB = j0 + r + 8;
            float wA = (jA <= i) ? sqrtf(nA) : -1e30f;
            float wB = (jB <= i) ? sqrtf(nB) : -1e30f;

            float mN = fmaxf(m, fmaxf(wA, wB));
            float c  = __expf(m - mN);
            float eA = __expf(wA - mN);
            float eB = __expf(wB - mN);
            s = s * c + eA + eB;
            m = mN;
            unsigned long long c2 = bcast2(c), eA2 = bcast2(eA), eB2 = bcast2(eB);
#pragma unroll
            for (int nt = 0; nt < 6; nt++) {
                unsigned long long bb = b2v[4 * nt + q];
                unsigned long long pa, pb;
                asm("add.rn.f32x2 %0, %1, %2;" : "=l"(pa)
                    : "l"(pack2(acc[nt][0], acc[nt][1])), "l"(bb));
                asm("add.rn.f32x2 %0, %1, %2;" : "=l"(pb)
                    : "l"(pack2(acc[nt][2], acc[nt][3])), "l"(bb));
                asm("mul.rn.f32x2 %0, %0, %1;"     : "+l"(o2[nt]) : "l"(c2));
                asm("fma.rn.f32x2 %0, %1, %2, %0;" : "+l"(o2[nt]) : "l"(pa), "l"(eA2));
                asm("fma.rn.f32x2 %0, %1, %2, %0;" : "+l"(o2[nt]) : "l"(pb), "l"(eB2));
            }
        }
    }

    // ---- merge the 8 r-groups within each warp (preserving q feature lanes) ----
#pragma unroll
    for (int off = 4; off <= 16; off <<= 1) {
        float mo = __shfl_xor_sync(full, m, off);
        float so = __shfl_xor_sync(full, s, off);
        float mN = fmaxf(m, mo);
        float fs = __expf(m - mN);
        float fo = __expf(mo - mN);
        s = s * fs + so * fo;
        unsigned long long fs2 = bcast2(fs), fo2 = bcast2(fo);
#pragma unroll
        for (int nt = 0; nt < 6; nt++) {
            unsigned long long t = __shfl_xor_sync(full, o2[nt], off);
            asm("mul.rn.f32x2 %0, %0, %1;"     : "+l"(o2[nt]) : "l"(fs2));
            asm("fma.rn.f32x2 %0, %1, %2, %0;" : "+l"(o2[nt]) : "l"(t), "l"(fo2));
        }
        m = mN;
    }

    if (lane < 4) {                    // lanes 0..3 carry q=0..3 warp results
        if (lane == 0) { red_m[w] = m; red_s[w] = s; }
#pragma unroll
        for (int nt = 0; nt < 6; nt++) {
            unsigned lo, hi;
            asm("mov.b64 {%0, %1}, %2;" : "=r"(lo), "=r"(hi) : "l"(o2[nt]));
            red_o[w][8 * nt + 2 * q]     = __uint_as_float(lo);
            red_o[w][8 * nt + 2 * q + 1] = __uint_as_float(hi);
        }
    }
    __syncthreads();

    if (tid < DFEAT) {
        float M = fmaxf(fmaxf(red_m[0], red_m[1]), fmaxf(red_m[2], red_m[3]));
        float S = 0.f, O = 0.f;
#pragma unroll
        for (int ww = 0; ww < 4; ww++) {
            float f = __expf(red_m[ww] - M);   // 0 for idle warps
            S += red_s[ww] * f;
            O += red_o[ww][tid] * f;
        }
        out[(b * NSEQ + i) * DFEAT + tid] = O / S;
    }
}

extern "C" void kernel_launch(void* const* d_in, const int* in_sizes, int n_in,
                              void* d_out, int out_size) {
    const float* x  = (const float*)d_in[0];
    const float* W1 = (const float*)d_in[1];
    const float* b1 = (const float*)d_in[2];
    const float* W2 = (const float*)d_in[3];
    const float* b2 = (const float*)d_in[4];
    float* out = (float*)d_out;

    precompute_kernel<<<4 * NSEQ, DH>>>(x, W1, b1);
    dim3 grid(NSEQ, 4);
    pair_kernel<<<grid, TPB>>>(W2, b2, out);
}

// round 13
// speedup vs baseline: 2.1267x; 1.1285x over previous
#include <cuda_runtime.h>
#include <cuda_bf16.h>
#include <cstdint>

#define NSEQ 512
#define DFEAT 48
#define DH 96
#define TPB 128

// Factored first-layer projections.
// g_A[b][i][k] = sum_c x[b,i,c]*W1[c,k] + b1[k]
// g_B[b][j][k] = sum_c x[b,j,c]*W1[48+c,k]
__device__ float g_A[4 * NSEQ * DH];
__device__ float g_B[4 * NSEQ * DH];

__global__ void precompute_kernel(const float* __restrict__ x,
                                  const float* __restrict__ W1,
                                  const float* __restrict__ b1) {
    int row = blockIdx.x;            // b*N + i
    __shared__ float sx[DFEAT];
    int t = threadIdx.x;             // 0..95
    if (t < DFEAT) sx[t] = x[row * DFEAT + t];
    __syncthreads();
    float a = b1[t];
    float bb = 0.f;
#pragma unroll
    for (int c = 0; c < DFEAT; c++) {
        float xv = sx[c];
        a  = fmaf(xv, W1[c * DH + t], a);
        bb = fmaf(xv, W1[(DFEAT + c) * DH + t], bb);
    }
    g_A[row * DH + t] = a;
    g_B[row * DH + t] = bb;
}

__device__ __forceinline__ unsigned long long bcast2(float v) {
    unsigned long long r;
    asm("mov.b64 %0, {%1, %1};" : "=l"(r) : "r"(__float_as_uint(v)));
    return r;
}
__device__ __forceinline__ unsigned long long pack2(float lo, float hi) {
    unsigned long long r;
    asm("mov.b64 %0, {%1, %2};" : "=l"(r) : "r"(__float_as_uint(lo)), "r"(__float_as_uint(hi)));
    return r;
}
__device__ __forceinline__ uint32_t packbf(float lo, float hi) {
    uint32_t d;
    asm("cvt.rn.bf16x2.f32 %0, %1, %2;" : "=r"(d) : "f"(hi), "f"(lo));
    return d;
}

// Packed-constant bundle for the f32x2 gelu chain (polynomial coefficients
// sign-flipped so q' = -q and E = fma(k*q', e, 1) needs no negate).
struct GC {
    unsigned long long nl, Aa, one2, half2, p5, p4, p3, p2, p1;
};

// Branchless exact-GELU on a packed pair (A-S 7.1.26 erf, |err|<=1.5e-7).
__device__ __forceinline__ unsigned long long gelu2(unsigned long long x2, const GC& C) {
    unsigned long long ax2, xx2, t2, e2p, kd2, k2, q2, kq2, E2, in2, g2;
    asm("and.b64 %0, %1, 0x7FFFFFFF7FFFFFFF;" : "=l"(ax2) : "l"(x2));
    asm("mul.rn.f32x2 %0, %1, %1;" : "=l"(xx2) : "l"(x2));
    asm("mul.rn.f32x2 %0, %1, %2;" : "=l"(t2) : "l"(xx2), "l"(C.nl));
    uint32_t tl, th;
    asm("mov.b64 {%0,%1}, %2;" : "=r"(tl), "=r"(th) : "l"(t2));
    float e0, e1;
    asm("ex2.approx.f32 %0, %1;" : "=f"(e0) : "f"(__uint_as_float(tl)));
    asm("ex2.approx.f32 %0, %1;" : "=f"(e1) : "f"(__uint_as_float(th)));
    e2p = pack2(e0, e1);
    asm("fma.rn.f32x2 %0, %1, %2, %3;" : "=l"(kd2) : "l"(ax2), "l"(C.Aa), "l"(C.one2));
    uint32_t kl, kh;
    asm("mov.b64 {%0,%1}, %2;" : "=r"(kl), "=r"(kh) : "l"(kd2));
    float k0f, k1f;
    asm("rcp.approx.f32 %0, %1;" : "=f"(k0f) : "f"(__uint_as_float(kl)));
    asm("rcp.approx.f32 %0, %1;" : "=f"(k1f) : "f"(__uint_as_float(kh)));
    k2 = pack2(k0f, k1f);
    asm("fma.rn.f32x2 %0, %1, %2, %3;" : "=l"(q2) : "l"(k2), "l"(C.p5), "l"(C.p4));
    asm("fma.rn.f32x2 %0, %1, %2, %3;" : "=l"(q2) : "l"(k2), "l"(q2), "l"(C.p3));
    asm("fma.rn.f32x2 %0, %1, %2, %3;" : "=l"(q2) : "l"(k2), "l"(q2), "l"(C.p2));
    asm("fma.rn.f32x2 %0, %1, %2, %3;" : "=l"(q2) : "l"(k2), "l"(q2), "l"(C.p1));
    asm("mul.rn.f32x2 %0, %1, %2;" : "=l"(kq2) : "l"(k2), "l"(q2));   // = -k*q
    asm("fma.rn.f32x2 %0, %1, %2, %3;" : "=l"(E2) : "l"(kq2), "l"(e2p), "l"(C.one2));
    asm("fma.rn.f32x2 %0, %1, %2, %3;" : "=l"(in2) : "l"(ax2), "l"(E2), "l"(x2));
    asm("mul.rn.f32x2 %0, %1, %2;" : "=l"(g2) : "l"(in2), "l"(C.half2));
    return g2;
}

// Split a packed gelu pair (g0,g1) into bf16x2 hi word + bf16x2 residue word.
__device__ __forceinline__ void tosplit(unsigned long long g2, uint32_t& hw, uint32_t& lw) {
    uint32_t g0, g1;
    asm("mov.b64 {%0,%1}, %2;" : "=r"(g0), "=r"(g1) : "l"(g2));
    hw = packbf(__uint_as_float(g0), __uint_as_float(g1));
    unsigned long long hi2 = pack2(__uint_as_float(hw << 16),
                                   __uint_as_float(hw & 0xffff0000u));
    unsigned long long r2;
    asm("sub.rn.f32x2 %0, %1, %2;" : "=l"(r2) : "l"(g2), "l"(hi2));
    uint32_t r0, r1;
    asm("mov.b64 {%0,%1}, %2;" : "=r"(r0), "=r"(r1) : "l"(r2));
    lw = packbf(__uint_as_float(r0), __uint_as_float(r1));
}

__device__ __forceinline__ void hmma(float* c, uint32_t a0, uint32_t a1,
                                     uint32_t a2, uint32_t a3,
                                     uint32_t b0, uint32_t b1) {
    asm volatile(
        "mma.sync.aligned.m16n8k16.row.col.f32.bf16.bf16.f32 "
        "{%0,%1,%2,%3}, {%4,%5,%6,%7}, {%8,%9}, {%0,%1,%2,%3};"
        : "+f"(c[0]), "+f"(c[1]), "+f"(c[2]), "+f"(c[3])
        : "r"(a0), "r"(a1), "r"(a2), "r"(a3), "r"(b0), "r"(b1));
}

// One CTA per output row (b,i). 4 warps; m16 j-tile t (rows 16t..16t+15) is
// handled by warp t%4 (flat round-robin => per-warp imbalance <= 1 tile).
// gelu computed packed f32x2, split hi/lo bf16; p = h@W2 + b2 via 3 HMMA
// passes (hi*hi + lo*hi + hi*lo) with acc initialized to b2.
__global__ void __launch_bounds__(TPB, 5) pair_kernel(const float* __restrict__ W2,
                                                      const float* __restrict__ b2,
                                                      float* __restrict__ out) {
    const int i = (int)(gridDim.x - 1 - blockIdx.x);   // longest rows first
    const int b = blockIdx.y;
    const int tid = threadIdx.x;
    const int w = tid >> 5;
    const int lane = tid & 31;
    const int q = lane & 3;        // thread within group of 4
    const int r = lane >> 2;       // group id 0..7

    __shared__ __align__(16) unsigned long long sBhi[36 * 32];  // 9 KB
    __shared__ __align__(16) unsigned long long sBlo[36 * 32];  // 9 KB
    __shared__ __align__(16) float sA[DH];
    __shared__ float red_m[4], red_s[4];
    __shared__ __align__(16) float red_o[4][DFEAT];

    // Stage W2 B-fragments (hi/lo) per (ktile, ntile, lane).
    for (int t36 = w; t36 < 36; t36 += 4) {
        int kt = t36 / 6, nt = t36 - kt * 6;
        int k0 = 16 * kt + 2 * q;
        int n = 8 * nt + r;
        float w00 = W2[k0 * DFEAT + n];
        float w01 = W2[(k0 + 1) * DFEAT + n];
        float w10 = W2[(k0 + 8) * DFEAT + n];
        float w11 = W2[(k0 + 9) * DFEAT + n];
        uint32_t b0h = packbf(w00, w01);
        uint32_t b1h = packbf(w10, w11);
        uint32_t b0l = packbf(w00 - __uint_as_float(b0h << 16),
                              w01 - __uint_as_float(b0h & 0xffff0000u));
        uint32_t b1l = packbf(w10 - __uint_as_float(b1h << 16),
                              w11 - __uint_as_float(b1h & 0xffff0000u));
        unsigned long long vh, vl;
        asm("mov.b64 %0, {%1, %2};" : "=l"(vh) : "r"(b0h), "r"(b1h));
        asm("mov.b64 %0, {%1, %2};" : "=l"(vl) : "r"(b0l), "r"(b1l));
        sBhi[t36 * 32 + lane] = vh;
        sBlo[t36 * 32 + lane] = vl;
    }
    if (tid < DH) sA[tid] = g_A[(b * NSEQ + i) * DH + tid];
    __syncthreads();

    GC C;
    C.nl = bcast2(-0.72134752044448170368f);
    C.Aa = bcast2(0.23164408767166038f);
    C.one2 = bcast2(1.0f);
    C.half2 = bcast2(0.5f);
    C.p5 = bcast2(-1.061405429f);
    C.p4 = bcast2(1.453152027f);
    C.p3 = bcast2(-1.421413741f);
    C.p2 = bcast2(0.284496736f);
    C.p1 = bcast2(-0.254829592f);

    // This thread's b2 values (cols 8nt+2q, 8nt+2q+1), also acc initializers.
    float b2lo[6], b2hi[6];
#pragma unroll
    for (int nt = 0; nt < 6; nt++) {
        b2lo[nt] = b2[8 * nt + 2 * q];
        b2hi[nt] = b2[8 * nt + 2 * q + 1];
    }

    const float* __restrict__ Bbase = g_B + b * NSEQ * DH;
    const unsigned full = 0xffffffffu;

    float m = -1e30f, s = 0.f;
    unsigned long long o2[6];
#pragma unroll
    for (int nt = 0; nt < 6; nt++) o2[nt] = 0ull;

    for (int t = w; 16 * t <= i; t += 4) {
        const int j0 = 16 * t;

        float acc[6][4];
#pragma unroll
        for (int nt = 0; nt < 6; nt++) {
            acc[nt][0] = b2lo[nt]; acc[nt][1] = b2hi[nt];
            acc[nt][2] = b2lo[nt]; acc[nt][3] = b2hi[nt];
        }

#pragma unroll
        for (int kt = 0; kt < 6; kt++) {
            const int c0 = 16 * kt + 2 * q;
            unsigned long long a0 = *(const unsigned long long*)&sA[c0];
            unsigned long long a1 = *(const unsigned long long*)&sA[c0 + 8];
            const int ro = (j0 + r) * DH + c0;
            unsigned long long x00 = *(const unsigned long long*)(Bbase + ro);
            unsigned long long x01 = *(const unsigned long long*)(Bbase + ro + 8);
            unsigned long long x10 = *(const unsigned long long*)(Bbase + ro + 8 * DH);
            unsigned long long x11 = *(const unsigned long long*)(Bbase + ro + 8 * DH + 8);
            unsigned long long p00, p01, p10, p11;
            asm("add.rn.f32x2 %0, %1, %2;" : "=l"(p00) : "l"(a0), "l"(x00));
            asm("add.rn.f32x2 %0, %1, %2;" : "=l"(p01) : "l"(a1), "l"(x01));
            asm("add.rn.f32x2 %0, %1, %2;" : "=l"(p10) : "l"(a0), "l"(x10));
            asm("add.rn.f32x2 %0, %1, %2;" : "=l"(p11) : "l"(a1), "l"(x11));
            unsigned long long g00 = gelu2(p00, C);
            unsigned long long g01 = gelu2(p01, C);
            unsigned long long g10 = gelu2(p10, C);
            unsigned long long g11 = gelu2(p11, C);
            uint32_t a0h, a0l, a1h, a1l, a2h, a2l, a3h, a3l;
            tosplit(g00, a0h, a0l);    // A[r][2q..2q+1]
            tosplit(g10, a1h, a1l);    // A[r+8][2q..2q+1]
            tosplit(g01, a2h, a2l);    // A[r][2q+8..2q+9]
            tosplit(g11, a3h, a3l);    // A[r+8][2q+8..2q+9]

#pragma unroll
            for (int nt = 0; nt < 6; nt++) {
                unsigned long long vh = sBhi[(kt * 6 + nt) * 32 + lane];
                unsigned long long vl = sBlo[(kt * 6 + nt) * 32 + lane];
                uint32_t b0h, b1h, b0l, b1l;
                asm("mov.b64 {%0, %1}, %2;" : "=r"(b0h), "=r"(b1h) : "l"(vh));
                asm("mov.b64 {%0, %1}, %2;" : "=r"(b0l), "=r"(b1l) : "l"(vl));
                hmma(acc[nt], a0h, a1h, a2h, a3h, b0h, b1h);
                hmma(acc[nt], a0l, a1l, a2l, a3l, b0h, b1h);
                hmma(acc[nt], a0h, a1h, a2h, a3h, b0l, b1l);
            }
        }

        // ---- epilogue: rows jA=j0+r, jB=j0+r+8 (acc already = p) ----
        unsigned long long nA2 = 0ull, nB2 = 0ull;
#pragma unroll
        for (int nt = 0; nt < 6; nt++) {
            asm("fma.rn.f32x2 %0, %1, %1, %0;" : "+l"(nA2)
                : "l"(pack2(acc[nt][0], acc[nt][1])));
            asm("fma.rn.f32x2 %0, %1, %1, %0;" : "+l"(nB2)
                : "l"(pack2(acc[nt][2], acc[nt][3])));
        }
        unsigned lo, hi;
        asm("mov.b64 {%0, %1}, %2;" : "=r"(lo), "=r"(hi) : "l"(nA2));
        float nA = __uint_as_float(lo) + __uint_as_float(hi);
        asm("mov.b64 {%0, %1}, %2;" : "=r"(lo), "=r"(hi) : "l"(nB2));
        float nB = __uint_as_float(lo) + __uint_as_float(hi);
        nA += __shfl_xor_sync(full, nA, 1, 4);
        nA += __shfl_xor_sync(full, nA, 2, 4);
        nB += __shfl_xor_sync(full, nB, 1, 4);
        nB += __shfl_xor_sync(full, nB, 2, 4);
        const int jA = j0 + r, jB = j0 + r + 8;
        float wA = (jA <= i) ? sqrtf(nA) : -1e30f;
        float wB = (jB <= i) ? sqrtf(nB) : -1e30f;

        float mN = fmaxf(m, fmaxf(wA, wB));
        float c  = __expf(m - mN);
        float eA = __expf(wA - mN);
        float eB = __expf(wB - mN);
        s = s * c + eA + eB;
        m = mN;
        unsigned long long c2 = bcast2(c), eA2 = bcast2(eA), eB2 = bcast2(eB);
#pragma unroll
        for (int nt = 0; nt < 6; nt++) {
            asm("mul.rn.f32x2 %0, %0, %1;" : "+l"(o2[nt]) : "l"(c2));
            asm("fma.rn.f32x2 %0, %1, %2, %0;" : "+l"(o2[nt])
                : "l"(pack2(acc[nt][0], acc[nt][1])), "l"(eA2));
            asm("fma.rn.f32x2 %0, %1, %2, %0;" : "+l"(o2[nt])
                : "l"(pack2(acc[nt][2], acc[nt][3])), "l"(eB2));
        }
    }

    // ---- merge the 8 r-groups within each warp (preserving q feature lanes) ----
#pragma unroll
    for (int off = 4; off <= 16; off <<= 1) {
        float mo = __shfl_xor_sync(full, m, off);
        float so = __shfl_xor_sync(full, s, off);
        float mN = fmaxf(m, mo);
        float fs = __expf(m - mN);
        float fo = __expf(mo - mN);
        s = s * fs + so * fo;
        unsigned long long fs2 = bcast2(fs), fo2 = bcast2(fo);
#pragma unroll
        for (int nt = 0; nt < 6; nt++) {
            unsigned long long t = __shfl_xor_sync(full, o2[nt], off);
            asm("mul.rn.f32x2 %0, %0, %1;"     : "+l"(o2[nt]) : "l"(fs2));
            asm("fma.rn.f32x2 %0, %1, %2, %0;" : "+l"(o2[nt]) : "l"(t), "l"(fo2));
        }
        m = mN;
    }

    if (lane < 4) {                    // lanes 0..3 carry q=0..3 warp results
        if (lane == 0) { red_m[w] = m; red_s[w] = s; }
#pragma unroll
        for (int nt = 0; nt < 6; nt++) {
            unsigned lo, hi;
            asm("mov.b64 {%0, %1}, %2;" : "=r"(lo), "=r"(hi) : "l"(o2[nt]));
            red_o[w][8 * nt + 2 * q]     = __uint_as_float(lo);
            red_o[w][8 * nt + 2 * q + 1] = __uint_as_float(hi);
        }
    }
    __syncthreads();

    if (tid < DFEAT) {
        float M = fmaxf(fmaxf(red_m[0], red_m[1]), fmaxf(red_m[2], red_m[3]));
        float S = 0.f, O = 0.f;
#pragma unroll
        for (int ww = 0; ww < 4; ww++) {
            float f = __expf(red_m[ww] - M);   // 0 for idle warps
            S += red_s[ww] * f;
            O += red_o[ww][tid] * f;
        }
        out[(b * NSEQ + i) * DFEAT + tid] = O / S;
    }
}

extern "C" void kernel_launch(void* const* d_in, const int* in_sizes, int n_in,
                              void* d_out, int out_size) {
    const float* x  = (const float*)d_in[0];
    const float* W1 = (const float*)d_in[1];
    const float* b1 = (const float*)d_in[2];
    const float* W2 = (const float*)d_in[3];
    const float* b2 = (const float*)d_in[4];
    float* out = (float*)d_out;

    precompute_kernel<<<4 * NSEQ, DH>>>(x, W1, b1);
    dim3 grid(NSEQ, 4);
    pair_kernel<<<grid, TPB>>>(W2, b2, out);
}

// round 14
// speedup vs baseline: 2.2218x; 1.0447x over previous
#include <cuda_runtime.h>
#include <cuda_bf16.h>
#include <cstdint>

#define NSEQ 512
#define DFEAT 48
#define DH 96
#define TPB 128

// Factored first-layer projections.
// g_A[b][i][k] = sum_c x[b,i,c]*W1[c,k] + b1[k]
// g_B[b][j][k] = sum_c x[b,j,c]*W1[48+c,k]
__device__ float g_A[4 * NSEQ * DH];
__device__ float g_B[4 * NSEQ * DH];

__global__ void precompute_kernel(const float* __restrict__ x,
                                  const float* __restrict__ W1,
                                  const float* __restrict__ b1) {
    int row = blockIdx.x;            // b*N + i
    __shared__ float sx[DFEAT];
    int t = threadIdx.x;             // 0..95
    if (t < DFEAT) sx[t] = x[row * DFEAT + t];
    __syncthreads();
    float a = b1[t];
    float bb = 0.f;
#pragma unroll
    for (int c = 0; c < DFEAT; c++) {
        float xv = sx[c];
        a  = fmaf(xv, W1[c * DH + t], a);
        bb = fmaf(xv, W1[(DFEAT + c) * DH + t], bb);
    }
    g_A[row * DH + t] = a;
    g_B[row * DH + t] = bb;
}

__device__ __forceinline__ unsigned long long bcast2(float v) {
    unsigned long long r;
    asm("mov.b64 %0, {%1, %1};" : "=l"(r) : "r"(__float_as_uint(v)));
    return r;
}
__device__ __forceinline__ unsigned long long pack2(float lo, float hi) {
    unsigned long long r;
    asm("mov.b64 %0, {%1, %2};" : "=l"(r) : "r"(__float_as_uint(lo)), "r"(__float_as_uint(hi)));
    return r;
}
__device__ __forceinline__ uint32_t totf(float f) {
    uint32_t d;
    asm("cvt.rna.tf32.f32 %0, %1;" : "=r"(d) : "f"(f));
    return d;
}

// Packed-constant bundle for the f32x2 gelu chain (polynomial coefficients
// sign-flipped so q' = -q and E = fma(k*q', e, 1) needs no negate).
struct GC {
    unsigned long long nl, Aa, one2, half2, p5, p4, p3, p2, p1;
};

// Branchless exact-GELU on a packed pair (A-S 7.1.26 erf, |err|<=1.5e-7).
__device__ __forceinline__ unsigned long long gelu2(unsigned long long x2, const GC& C) {
    unsigned long long ax2, xx2, t2, e2p, kd2, k2, q2, kq2, E2, in2, g2;
    asm("and.b64 %0, %1, 0x7FFFFFFF7FFFFFFF;" : "=l"(ax2) : "l"(x2));
    asm("mul.rn.f32x2 %0, %1, %1;" : "=l"(xx2) : "l"(x2));
    asm("mul.rn.f32x2 %0, %1, %2;" : "=l"(t2) : "l"(xx2), "l"(C.nl));
    uint32_t tl, th;
    asm("mov.b64 {%0,%1}, %2;" : "=r"(tl), "=r"(th) : "l"(t2));
    float e0, e1;
    asm("ex2.approx.f32 %0, %1;" : "=f"(e0) : "f"(__uint_as_float(tl)));
    asm("ex2.approx.f32 %0, %1;" : "=f"(e1) : "f"(__uint_as_float(th)));
    e2p = pack2(e0, e1);
    asm("fma.rn.f32x2 %0, %1, %2, %3;" : "=l"(kd2) : "l"(ax2), "l"(C.Aa), "l"(C.one2));
    uint32_t kl, kh;
    asm("mov.b64 {%0,%1}, %2;" : "=r"(kl), "=r"(kh) : "l"(kd2));
    float k0f, k1f;
    asm("rcp.approx.f32 %0, %1;" : "=f"(k0f) : "f"(__uint_as_float(kl)));
    asm("rcp.approx.f32 %0, %1;" : "=f"(k1f) : "f"(__uint_as_float(kh)));
    k2 = pack2(k0f, k1f);
    asm("fma.rn.f32x2 %0, %1, %2, %3;" : "=l"(q2) : "l"(k2), "l"(C.p5), "l"(C.p4));
    asm("fma.rn.f32x2 %0, %1, %2, %3;" : "=l"(q2) : "l"(k2), "l"(q2), "l"(C.p3));
    asm("fma.rn.f32x2 %0, %1, %2, %3;" : "=l"(q2) : "l"(k2), "l"(q2), "l"(C.p2));
    asm("fma.rn.f32x2 %0, %1, %2, %3;" : "=l"(q2) : "l"(k2), "l"(q2), "l"(C.p1));
    asm("mul.rn.f32x2 %0, %1, %2;" : "=l"(kq2) : "l"(k2), "l"(q2));   // = -k*q
    asm("fma.rn.f32x2 %0, %1, %2, %3;" : "=l"(E2) : "l"(kq2), "l"(e2p), "l"(C.one2));
    asm("fma.rn.f32x2 %0, %1, %2, %3;" : "=l"(in2) : "l"(ax2), "l"(E2), "l"(x2));
    asm("mul.rn.f32x2 %0, %1, %2;" : "=l"(g2) : "l"(in2), "l"(C.half2));
    return g2;
}

__device__ __forceinline__ void hmma_tf32(float* c, uint32_t a0, uint32_t a1,
                                          uint32_t a2, uint32_t a3,
                                          uint32_t b0, uint32_t b1) {
    asm volatile(
        "mma.sync.aligned.m16n8k8.row.col.f32.tf32.tf32.f32 "
        "{%0,%1,%2,%3}, {%4,%5,%6,%7}, {%8,%9}, {%0,%1,%2,%3};"
        : "+f"(c[0]), "+f"(c[1]), "+f"(c[2]), "+f"(c[3])
        : "r"(a0), "r"(a1), "r"(a2), "r"(a3), "r"(b0), "r"(b1));
}

// One CTA per output row (b,i). 4 warps; m16 j-tile t (rows 16t..16t+15) goes
// to warp t%4. gelu computed packed f32x2; p = h@W2 + b2 via single-pass tf32
// MMA (m16n8k8) with acc initialized to b2. k-columns are assigned so thread
// q's (a0,a2) are ADJACENT global columns 8kt+2q, 8kt+2q+1 (B staged to match)
// -> packed LDG.64 + packed gelu feed the A fragment directly.
__global__ void __launch_bounds__(TPB, 5) pair_kernel(const float* __restrict__ W2,
                                                      const float* __restrict__ b2,
                                                      float* __restrict__ out) {
    const int i = (int)(gridDim.x - 1 - blockIdx.x);   // longest rows first
    const int b = blockIdx.y;
    const int tid = threadIdx.x;
    const int w = tid >> 5;
    const int lane = tid & 31;
    const int q = lane & 3;        // thread within group of 4
    const int r = lane >> 2;       // group id 0..7

    // B fragments: [kt*3+ntp][lane] = { (b0,b1) for nt=2ntp, (b0,b1) for nt=2ntp+1 }
    __shared__ __align__(16) ulonglong2 sB[36 * 32];   // 18 KB
    __shared__ __align__(16) float sA[DH];
    __shared__ float red_m[4], red_s[4];
    __shared__ __align__(16) float red_o[4][DFEAT];

    // Stage W2 tf32 B-fragments: tile-row q holds global k = 8kt+2q,
    // tile-row q+4 holds global k = 8kt+2q+1.
    for (int s36 = w; s36 < 36; s36 += 4) {
        int kt = s36 / 3, ntp = s36 - kt * 3;
        int k0 = 8 * kt + 2 * q;
        int n0 = 8 * (2 * ntp) + r;
        int n1 = 8 * (2 * ntp + 1) + r;
        uint32_t b0a = totf(W2[k0 * DFEAT + n0]);
        uint32_t b1a = totf(W2[(k0 + 1) * DFEAT + n0]);
        uint32_t b0b = totf(W2[k0 * DFEAT + n1]);
        uint32_t b1b = totf(W2[(k0 + 1) * DFEAT + n1]);
        ulonglong2 v;
        asm("mov.b64 %0, {%1, %2};" : "=l"(v.x) : "r"(b0a), "r"(b1a));
        asm("mov.b64 %0, {%1, %2};" : "=l"(v.y) : "r"(b0b), "r"(b1b));
        sB[s36 * 32 + lane] = v;
    }
    if (tid < DH) sA[tid] = g_A[(b * NSEQ + i) * DH + tid];
    __syncthreads();

    GC C;
    C.nl = bcast2(-0.72134752044448170368f);
    C.Aa = bcast2(0.23164408767166038f);
    C.one2 = bcast2(1.0f);
    C.half2 = bcast2(0.5f);
    C.p5 = bcast2(-1.061405429f);
    C.p4 = bcast2(1.453152027f);
    C.p3 = bcast2(-1.421413741f);
    C.p2 = bcast2(0.284496736f);
    C.p1 = bcast2(-0.254829592f);

    // This thread's b2 values (cols 8nt+2q, 8nt+2q+1) = acc initializers.
    float b2lo[6], b2hi[6];
#pragma unroll
    for (int nt = 0; nt < 6; nt++) {
        b2lo[nt] = b2[8 * nt + 2 * q];
        b2hi[nt] = b2[8 * nt + 2 * q + 1];
    }

    const float* __restrict__ Bbase = g_B + b * NSEQ * DH;
    const unsigned full = 0xffffffffu;

    float m = -1e30f, s = 0.f;
    unsigned long long o2[6];
#pragma unroll
    for (int nt = 0; nt < 6; nt++) o2[nt] = 0ull;

    for (int t = w; 16 * t <= i; t += 4) {
        const int j0 = 16 * t;

        float acc[6][4];
#pragma unroll
        for (int nt = 0; nt < 6; nt++) {
            acc[nt][0] = b2lo[nt]; acc[nt][1] = b2hi[nt];
            acc[nt][2] = b2lo[nt]; acc[nt][3] = b2hi[nt];
        }

#pragma unroll
        for (int kt = 0; kt < 12; kt++) {
            const int c0 = 8 * kt + 2 * q;
            unsigned long long aP = *(const unsigned long long*)&sA[c0];
            const int ro = (j0 + r) * DH + c0;
            unsigned long long xA = *(const unsigned long long*)(Bbase + ro);
            unsigned long long xB = *(const unsigned long long*)(Bbase + ro + 8 * DH);
            unsigned long long pA, pB;
            asm("add.rn.f32x2 %0, %1, %2;" : "=l"(pA) : "l"(aP), "l"(xA));
            asm("add.rn.f32x2 %0, %1, %2;" : "=l"(pB) : "l"(aP), "l"(xB));
            unsigned long long gA = gelu2(pA, C);
            unsigned long long gB = gelu2(pB, C);
            uint32_t gA0, gA1, gB0, gB1;
            asm("mov.b64 {%0,%1}, %2;" : "=r"(gA0), "=r"(gA1) : "l"(gA));
            asm("mov.b64 {%0,%1}, %2;" : "=r"(gB0), "=r"(gB1) : "l"(gB));
            uint32_t a0 = totf(__uint_as_float(gA0));   // A[r][k=8kt+2q]
            uint32_t a2 = totf(__uint_as_float(gA1));   // A[r][k=8kt+2q+1]
            uint32_t a1 = totf(__uint_as_float(gB0));   // A[r+8][k=8kt+2q]
            uint32_t a3 = totf(__uint_as_float(gB1));   // A[r+8][k=8kt+2q+1]

#pragma unroll
            for (int ntp = 0; ntp < 3; ntp++) {
                ulonglong2 v = sB[(kt * 3 + ntp) * 32 + lane];
                uint32_t b0a, b1a, b0b, b1b;
                asm("mov.b64 {%0, %1}, %2;" : "=r"(b0a), "=r"(b1a) : "l"(v.x));
                asm("mov.b64 {%0, %1}, %2;" : "=r"(b0b), "=r"(b1b) : "l"(v.y));
                hmma_tf32(acc[2 * ntp],     a0, a1, a2, a3, b0a, b1a);
                hmma_tf32(acc[2 * ntp + 1], a0, a1, a2, a3, b0b, b1b);
            }
        }

        // ---- epilogue: rows jA=j0+r, jB=j0+r+8 (acc already = p) ----
        unsigned long long nA2 = 0ull, nB2 = 0ull;
#pragma unroll
        for (int nt = 0; nt < 6; nt++) {
            asm("fma.rn.f32x2 %0, %1, %1, %0;" : "+l"(nA2)
                : "l"(pack2(acc[nt][0], acc[nt][1])));
            asm("fma.rn.f32x2 %0, %1, %1, %0;" : "+l"(nB2)
                : "l"(pack2(acc[nt][2], acc[nt][3])));
        }
        unsigned lo, hi;
        asm("mov.b64 {%0, %1}, %2;" : "=r"(lo), "=r"(hi) : "l"(nA2));
        float nA = __uint_as_float(lo) + __uint_as_float(hi);
        asm("mov.b64 {%0, %1}, %2;" : "=r"(lo), "=r"(hi) : "l"(nB2));
        float nB = __uint_as_float(lo) + __uint_as_float(hi);
        nA += __shfl_xor_sync(full, nA, 1, 4);
        nA += __shfl_xor_sync(full, nA, 2, 4);
        nB += __shfl_xor_sync(full, nB, 1, 4);
        nB += __shfl_xor_sync(full, nB, 2, 4);
        const int jA = j0 + r, jB = j0 + r + 8;
        float wA = (jA <= i) ? sqrtf(nA) : -1e30f;
        float wB = (jB <= i) ? sqrtf(nB) : -1e30f;

        float mN = fmaxf(m, fmaxf(wA, wB));
        float c  = __expf(m - mN);
        float eA = __expf(wA - mN);
        float eB = __expf(wB - mN);
        s = s * c + eA + eB;
        m = mN;
        unsigned long long c2 = bcast2(c), eA2 = bcast2(eA), eB2 = bcast2(eB);
#pragma unroll
        for (int nt = 0; nt < 6; nt++) {
            asm("mul.rn.f32x2 %0, %0, %1;" : "+l"(o2[nt]) : "l"(c2));
            asm("fma.rn.f32x2 %0, %1, %2, %0;" : "+l"(o2[nt])
                : "l"(pack2(acc[nt][0], acc[nt][1])), "l"(eA2));
            asm("fma.rn.f32x2 %0, %1, %2, %0;" : "+l"(o2[nt])
                : "l"(pack2(acc[nt][2], acc[nt][3])), "l"(eB2));
        }
    }

    // ---- merge the 8 r-groups within each warp (preserving q feature lanes) ----
#pragma unroll
    for (int off = 4; off <= 16; off <<= 1) {
        float mo = __shfl_xor_sync(full, m, off);
        float so = __shfl_xor_sync(full, s, off);
        float mN = fmaxf(m, mo);
        float fs = __expf(m - mN);
        float fo = __expf(mo - mN);
        s = s * fs + so * fo;
        unsigned long long fs2 = bcast2(fs), fo2 = bcast2(fo);
#pragma unroll
        for (int nt = 0; nt < 6; nt++) {
            unsigned long long t = __shfl_xor_sync(full, o2[nt], off);
            asm("mul.rn.f32x2 %0, %0, %1;"     : "+l"(o2[nt]) : "l"(fs2));
            asm("fma.rn.f32x2 %0, %1, %2, %0;" : "+l"(o2[nt]) : "l"(t), "l"(fo2));
        }
        m = mN;
    }

    if (lane < 4) {                    // lanes 0..3 carry q=0..3 warp results
        if (lane == 0) { red_m[w] = m; red_s[w] = s; }
#pragma unroll
        for (int nt = 0; nt < 6; nt++) {
            unsigned lo, hi;
            asm("mov.b64 {%0, %1}, %2;" : "=r"(lo), "=r"(hi) : "l"(o2[nt]));
            red_o[w][8 * nt + 2 * q]     = __uint_as_float(lo);
            red_o[w][8 * nt + 2 * q + 1] = __uint_as_float(hi);
        }
    }
    __syncthreads();

    if (tid < DFEAT) {
        float M = fmaxf(fmaxf(red_m[0], red_m[1]), fmaxf(red_m[2], red_m[3]));
        float S = 0.f, O = 0.f;
#pragma unroll
        for (int ww = 0; ww < 4; ww++) {
            float f = __expf(red_m[ww] - M);   // 0 for idle warps
            S += red_s[ww] * f;
            O += red_o[ww][tid] * f;
        }
        out[(b * NSEQ + i) * DFEAT + tid] = O / S;
    }
}

extern "C" void kernel_launch(void* const* d_in, const int* in_sizes, int n_in,
                              void* d_out, int out_size) {
    const float* x  = (const float*)d_in[0];
    const float* W1 = (const float*)d_in[1];
    const float* b1 = (const float*)d_in[2];
    const float* W2 = (const float*)d_in[3];
    const float* b2 = (const float*)d_in[4];
    float* out = (float*)d_out;

    precompute_kernel<<<4 * NSEQ, DH>>>(x, W1, b1);
    dim3 grid(NSEQ, 4);
    pair_kernel<<<grid, TPB>>>(W2, b2, out);
}

// round 15
// speedup vs baseline: 2.3856x; 1.0737x over previous
#include <cuda_runtime.h>
#include <cuda_bf16.h>
#include <cstdint>

#define NSEQ 512
#define DFEAT 48
#define DH 96
#define TPB 128

// Factored first-layer projections.
// g_A[b][i][k] = sum_c x[b,i,c]*W1[c,k] + b1[k]
// g_B[b][j][k] = sum_c x[b,j,c]*W1[48+c,k]
__device__ float g_A[4 * NSEQ * DH];
__device__ float g_B[4 * NSEQ * DH];

__global__ void precompute_kernel(const float* __restrict__ x,
                                  const float* __restrict__ W1,
                                  const float* __restrict__ b1) {
    int row = blockIdx.x;            // b*N + i
    __shared__ float sx[DFEAT];
    int t = threadIdx.x;             // 0..95
    if (t < DFEAT) sx[t] = x[row * DFEAT + t];
    __syncthreads();
    float a = b1[t];
    float bb = 0.f;
#pragma unroll
    for (int c = 0; c < DFEAT; c++) {
        float xv = sx[c];
        a  = fmaf(xv, W1[c * DH + t], a);
        bb = fmaf(xv, W1[(DFEAT + c) * DH + t], bb);
    }
    g_A[row * DH + t] = a;
    g_B[row * DH + t] = bb;
}

__device__ __forceinline__ unsigned long long bcast2(float v) {
    unsigned long long r;
    asm("mov.b64 %0, {%1, %1};" : "=l"(r) : "r"(__float_as_uint(v)));
    return r;
}
__device__ __forceinline__ unsigned long long pack2(float lo, float hi) {
    unsigned long long r;
    asm("mov.b64 %0, {%1, %2};" : "=l"(r) : "r"(__float_as_uint(lo)), "r"(__float_as_uint(hi)));
    return r;
}
__device__ __forceinline__ uint32_t totf(float f) {
    uint32_t d;
    asm("cvt.rna.tf32.f32 %0, %1;" : "=r"(d) : "f"(f));
    return d;
}

// Packed-constant bundle for the f32x2 gelu chain (polynomial coefficients
// sign-flipped so q' = -q and E = fma(k*q', e, 1) needs no negate).
struct GC {
    unsigned long long nl, Aa, one2, p5, p4, p3, p2, p1;
};

// Branchless 2x exact-GELU on a packed pair: returns in = x + |x|*erf(|x|/sqrt2)
// = 2*gelu(x). The 0.5 factor is folded into the staged W2. (A-S 7.1.26 erf.)
__device__ __forceinline__ unsigned long long gelu2x2(unsigned long long x2, const GC& C) {
    unsigned long long ax2, xx2, t2, e2p, kd2, k2, q2, kq2, E2, in2;
    asm("and.b64 %0, %1, 0x7FFFFFFF7FFFFFFF;" : "=l"(ax2) : "l"(x2));
    asm("mul.rn.f32x2 %0, %1, %1;" : "=l"(xx2) : "l"(x2));
    asm("mul.rn.f32x2 %0, %1, %2;" : "=l"(t2) : "l"(xx2), "l"(C.nl));
    uint32_t tl, th;
    asm("mov.b64 {%0,%1}, %2;" : "=r"(tl), "=r"(th) : "l"(t2));
    float e0, e1;
    asm("ex2.approx.f32 %0, %1;" : "=f"(e0) : "f"(__uint_as_float(tl)));
    asm("ex2.approx.f32 %0, %1;" : "=f"(e1) : "f"(__uint_as_float(th)));
    e2p = pack2(e0, e1);
    asm("fma.rn.f32x2 %0, %1, %2, %3;" : "=l"(kd2) : "l"(ax2), "l"(C.Aa), "l"(C.one2));
    uint32_t kl, kh;
    asm("mov.b64 {%0,%1}, %2;" : "=r"(kl), "=r"(kh) : "l"(kd2));
    float k0f, k1f;
    asm("rcp.approx.f32 %0, %1;" : "=f"(k0f) : "f"(__uint_as_float(kl)));
    asm("rcp.approx.f32 %0, %1;" : "=f"(k1f) : "f"(__uint_as_float(kh)));
    k2 = pack2(k0f, k1f);
    asm("fma.rn.f32x2 %0, %1, %2, %3;" : "=l"(q2) : "l"(k2), "l"(C.p5), "l"(C.p4));
    asm("fma.rn.f32x2 %0, %1, %2, %3;" : "=l"(q2) : "l"(k2), "l"(q2), "l"(C.p3));
    asm("fma.rn.f32x2 %0, %1, %2, %3;" : "=l"(q2) : "l"(k2), "l"(q2), "l"(C.p2));
    asm("fma.rn.f32x2 %0, %1, %2, %3;" : "=l"(q2) : "l"(k2), "l"(q2), "l"(C.p1));
    asm("mul.rn.f32x2 %0, %1, %2;" : "=l"(kq2) : "l"(k2), "l"(q2));   // = -k*q
    asm("fma.rn.f32x2 %0, %1, %2, %3;" : "=l"(E2) : "l"(kq2), "l"(e2p), "l"(C.one2));
    asm("fma.rn.f32x2 %0, %1, %2, %3;" : "=l"(in2) : "l"(ax2), "l"(E2), "l"(x2));
    return in2;
}

__device__ __forceinline__ void hmma_tf32(float* c, uint32_t a0, uint32_t a1,
                                          uint32_t a2, uint32_t a3,
                                          uint32_t b0, uint32_t b1) {
    asm volatile(
        "mma.sync.aligned.m16n8k8.row.col.f32.tf32.tf32.f32 "
        "{%0,%1,%2,%3}, {%4,%5,%6,%7}, {%8,%9}, {%0,%1,%2,%3};"
        : "+f"(c[0]), "+f"(c[1]), "+f"(c[2]), "+f"(c[3])
        : "r"(a0), "r"(a1), "r"(a2), "r"(a3), "r"(b0), "r"(b1));
}

// One CTA per output row (b,i). 4 warps; m16 j-tile t goes to warp t%4.
// gelu computed packed f32x2 (2x-scaled; 0.5 folded into W2); A fragments are
// RAW fp32 bits (tf32 = top 19 bits, HW truncates -> free conversion);
// p = in@(W2/2) + b2 via single-pass tf32 MMA with acc initialized to b2.
__global__ void __launch_bounds__(TPB, 5) pair_kernel(const float* __restrict__ W2,
                                                      const float* __restrict__ b2,
                                                      float* __restrict__ out) {
    const int i = (int)(gridDim.x - 1 - blockIdx.x);   // longest rows first
    const int b = blockIdx.y;
    const int tid = threadIdx.x;
    const int w = tid >> 5;
    const int lane = tid & 31;
    const int q = lane & 3;        // thread within group of 4
    const int r = lane >> 2;       // group id 0..7

    // B fragments: [kt*3+ntp][lane] = { (b0,b1) for nt=2ntp, (b0,b1) for nt=2ntp+1 }
    __shared__ __align__(16) ulonglong2 sB[36 * 32];   // 18 KB
    __shared__ __align__(16) float sA[DH];
    __shared__ float red_m[4], red_s[4];
    __shared__ __align__(16) float red_o[4][DFEAT];

    // Stage (W2 * 0.5) tf32 B-fragments: tile-row q holds global k = 8kt+2q,
    // tile-row q+4 holds global k = 8kt+2q+1.
    for (int s36 = w; s36 < 36; s36 += 4) {
        int kt = s36 / 3, ntp = s36 - kt * 3;
        int k0 = 8 * kt + 2 * q;
        int n0 = 8 * (2 * ntp) + r;
        int n1 = 8 * (2 * ntp + 1) + r;
        uint32_t b0a = totf(0.5f * W2[k0 * DFEAT + n0]);
        uint32_t b1a = totf(0.5f * W2[(k0 + 1) * DFEAT + n0]);
        uint32_t b0b = totf(0.5f * W2[k0 * DFEAT + n1]);
        uint32_t b1b = totf(0.5f * W2[(k0 + 1) * DFEAT + n1]);
        ulonglong2 v;
        asm("mov.b64 %0, {%1, %2};" : "=l"(v.x) : "r"(b0a), "r"(b1a));
        asm("mov.b64 %0, {%1, %2};" : "=l"(v.y) : "r"(b0b), "r"(b1b));
        sB[s36 * 32 + lane] = v;
    }
    if (tid < DH) sA[tid] = g_A[(b * NSEQ + i) * DH + tid];
    __syncthreads();

    GC C;
    C.nl = bcast2(-0.72134752044448170368f);
    C.Aa = bcast2(0.23164408767166038f);
    C.one2 = bcast2(1.0f);
    C.p5 = bcast2(-1.061405429f);
    C.p4 = bcast2(1.453152027f);
    C.p3 = bcast2(-1.421413741f);
    C.p2 = bcast2(0.284496736f);
    C.p1 = bcast2(-0.254829592f);

    // This thread's b2 values (cols 8nt+2q, 8nt+2q+1) = acc initializers.
    float b2lo[6], b2hi[6];
#pragma unroll
    for (int nt = 0; nt < 6; nt++) {
        b2lo[nt] = b2[8 * nt + 2 * q];
        b2hi[nt] = b2[8 * nt + 2 * q + 1];
    }

    const float* __restrict__ Bbase = g_B + b * NSEQ * DH;
    const unsigned full = 0xffffffffu;

    float m = -1e30f, s = 0.f;
    unsigned long long o2[6];
#pragma unroll
    for (int nt = 0; nt < 6; nt++) o2[nt] = 0ull;

    for (int t = w; 16 * t <= i; t += 4) {
        const int j0 = 16 * t;

        float acc[6][4];
#pragma unroll
        for (int nt = 0; nt < 6; nt++) {
            acc[nt][0] = b2lo[nt]; acc[nt][1] = b2hi[nt];
            acc[nt][2] = b2lo[nt]; acc[nt][3] = b2hi[nt];
        }

#pragma unroll
        for (int kt = 0; kt < 12; kt++) {
            const int c0 = 8 * kt + 2 * q;
            unsigned long long aP = *(const unsigned long long*)&sA[c0];
            const int ro = (j0 + r) * DH + c0;
            unsigned long long xA = *(const unsigned long long*)(Bbase + ro);
            unsigned long long xB = *(const unsigned long long*)(Bbase + ro + 8 * DH);
            unsigned long long pA, pB;
            asm("add.rn.f32x2 %0, %1, %2;" : "=l"(pA) : "l"(aP), "l"(xA));
            asm("add.rn.f32x2 %0, %1, %2;" : "=l"(pB) : "l"(aP), "l"(xB));
            unsigned long long gA = gelu2x2(pA, C);
            unsigned long long gB = gelu2x2(pB, C);
            uint32_t a0, a2, a1, a3;
            asm("mov.b64 {%0,%1}, %2;" : "=r"(a0), "=r"(a2) : "l"(gA));  // A[r][k], A[r][k+1]
            asm("mov.b64 {%0,%1}, %2;" : "=r"(a1), "=r"(a3) : "l"(gB));  // A[r+8][k], A[r+8][k+1]

#pragma unroll
            for (int ntp = 0; ntp < 3; ntp++) {
                ulonglong2 v = sB[(kt * 3 + ntp) * 32 + lane];
                uint32_t b0a, b1a, b0b, b1b;
                asm("mov.b64 {%0, %1}, %2;" : "=r"(b0a), "=r"(b1a) : "l"(v.x));
                asm("mov.b64 {%0, %1}, %2;" : "=r"(b0b), "=r"(b1b) : "l"(v.y));
                hmma_tf32(acc[2 * ntp],     a0, a1, a2, a3, b0a, b1a);
                hmma_tf32(acc[2 * ntp + 1], a0, a1, a2, a3, b0b, b1b);
            }
        }

        // ---- epilogue: rows jA=j0+r, jB=j0+r+8 (acc already = p) ----
        unsigned long long nA2 = 0ull, nB2 = 0ull;
#pragma unroll
        for (int nt = 0; nt < 6; nt++) {
            asm("fma.rn.f32x2 %0, %1, %1, %0;" : "+l"(nA2)
                : "l"(pack2(acc[nt][0], acc[nt][1])));
            asm("fma.rn.f32x2 %0, %1, %1, %0;" : "+l"(nB2)
                : "l"(pack2(acc[nt][2], acc[nt][3])));
        }
        unsigned lo, hi;
        asm("mov.b64 {%0, %1}, %2;" : "=r"(lo), "=r"(hi) : "l"(nA2));
        float nA = __uint_as_float(lo) + __uint_as_float(hi);
        asm("mov.b64 {%0, %1}, %2;" : "=r"(lo), "=r"(hi) : "l"(nB2));
        float nB = __uint_as_float(lo) + __uint_as_float(hi);
        nA += __shfl_xor_sync(full, nA, 1, 4);
        nA += __shfl_xor_sync(full, nA, 2, 4);
        nB += __shfl_xor_sync(full, nB, 1, 4);
        nB += __shfl_xor_sync(full, nB, 2, 4);
        const int jA = j0 + r, jB = j0 + r + 8;
        float sA_, sB_;
        asm("sqrt.approx.f32 %0, %1;" : "=f"(sA_) : "f"(nA));
        asm("sqrt.approx.f32 %0, %1;" : "=f"(sB_) : "f"(nB));
        float wA = (jA <= i) ? sA_ : -1e30f;
        float wB = (jB <= i) ? sB_ : -1e30f;

        float mN = fmaxf(m, fmaxf(wA, wB));
        float c  = __expf(m - mN);
        float eA = __expf(wA - mN);
        float eB = __expf(wB - mN);
        s = s * c + eA + eB;
        m = mN;
        unsigned long long c2 = bcast2(c), eA2 = bcast2(eA), eB2 = bcast2(eB);
#pragma unroll
        for (int nt = 0; nt < 6; nt++) {
            asm("mul.rn.f32x2 %0, %0, %1;" : "+l"(o2[nt]) : "l"(c2));
            asm("fma.rn.f32x2 %0, %1, %2, %0;" : "+l"(o2[nt])
                : "l"(pack2(acc[nt][0], acc[nt][1])), "l"(eA2));
            asm("fma.rn.f32x2 %0, %1, %2, %0;" : "+l"(o2[nt])
                : "l"(pack2(acc[nt][2], acc[nt][3])), "l"(eB2));
        }
    }

    // ---- merge the 8 r-groups within each warp (preserving q feature lanes) ----
#pragma unroll
    for (int off = 4; off <= 16; off <<= 1) {
        float mo = __shfl_xor_sync(full, m, off);
        float so = __shfl_xor_sync(full, s, off);
        float mN = fmaxf(m, mo);
        float fs = __expf(m - mN);
        float fo = __expf(mo - mN);
        s = s * fs + so * fo;
        unsigned long long fs2 = bcast2(fs), fo2 = bcast2(fo);
#pragma unroll
        for (int nt = 0; nt < 6; nt++) {
            unsigned long long t = __shfl_xor_sync(full, o2[nt], off);
            asm("mul.rn.f32x2 %0, %0, %1;"     : "+l"(o2[nt]) : "l"(fs2));
            asm("fma.rn.f32x2 %0, %1, %2, %0;" : "+l"(o2[nt]) : "l"(t), "l"(fo2));
        }
        m = mN;
    }

    if (lane < 4) {                    // lanes 0..3 carry q=0..3 warp results
        if (lane == 0) { red_m[w] = m; red_s[w] = s; }
#pragma unroll
        for (int nt = 0; nt < 6; nt++) {
            unsigned lo, hi;
            asm("mov.b64 {%0, %1}, %2;" : "=r"(lo), "=r"(hi) : "l"(o2[nt]));
            red_o[w][8 * nt + 2 * q]     = __uint_as_float(lo);
            red_o[w][8 * nt + 2 * q + 1] = __uint_as_float(hi);
        }
    }
    __syncthreads();

    if (tid < DFEAT) {
        float M = fmaxf(fmaxf(red_m[0], red_m[1]), fmaxf(red_m[2], red_m[3]));
        float S = 0.f, O = 0.f;
#pragma unroll
        for (int ww = 0; ww < 4; ww++) {
            float f = __expf(red_m[ww] - M);   // 0 for idle warps
            S += red_s[ww] * f;
            O += red_o[ww][tid] * f;
        }
        out[(b * NSEQ + i) * DFEAT + tid] = O / S;
    }
}

extern "C" void kernel_launch(void* const* d_in, const int* in_sizes, int n_in,
                              void* d_out, int out_size) {
    const float* x  = (const float*)d_in[0];
    const float* W1 = (const float*)d_in[1];
    const float* b1 = (const float*)d_in[2];
    const float* W2 = (const float*)d_in[3];
    const float* b2 = (const float*)d_in[4];
    float* out = (float*)d_out;

    precompute_kernel<<<4 * NSEQ, DH>>>(x, W1, b1);
    dim3 grid(NSEQ, 4);
    pair_kernel<<<grid, TPB>>>(W2, b2, out);
}